// round 2
// baseline (speedup 1.0000x reference)
#include <cuda_runtime.h>

#define H 128
#define NB 8
#define NV 1024
#define NM 64

// Scratch (device globals — no allocation allowed)
__device__ float g_WeffV[H * H];
__device__ float g_beffV[H];
__device__ float g_WeffL[H * H];
__device__ float g_beffL[H];
__device__ float g_vp[NB * NV * H];   // v_part (folded)  [8192,128]
__device__ float g_lb[NB * NM * H];   // l_part + b1      [512,128]

// ---------------------------------------------------------------------------
// Kernel 1: fold Wv@W1[H:] and Wl@W1[:H] (+ biases) into single 128x128 mats.
// grid (129, 2), 128 threads. row 128 = bias row.
// ---------------------------------------------------------------------------
__global__ void fold_kernel(const float* __restrict__ Wv, const float* __restrict__ bv,
                            const float* __restrict__ Wl, const float* __restrict__ bl,
                            const float* __restrict__ W1, const float* __restrict__ b1)
{
    int h = threadIdx.x;
    int row = blockIdx.x;      // 0..128
    int which = blockIdx.y;    // 0 = virtual, 1 = ligand
    const float* A;
    int w1off;
    if (which == 0) { A = (row < H) ? (Wv + row * H) : bv; w1off = H; }
    else            { A = (row < H) ? (Wl + row * H) : bl; w1off = 0; }
    float acc = 0.f;
#pragma unroll 8
    for (int hid = 0; hid < H; hid++)
        acc += A[hid] * W1[(w1off + hid) * H + h];
    if (row < H) {
        (which == 0 ? g_WeffV : g_WeffL)[row * H + h] = acc;
    } else {
        if (which == 1) acc += b1[h];
        (which == 0 ? g_beffV : g_beffL)[h] = acc;
    }
}

// ---------------------------------------------------------------------------
// Kernel 2: g_vp = virt @ WeffV + beffV   (8192 rows, blocks 0..255)
//           g_lb = lig  @ WeffL + beffL   (512 rows,  blocks 256..271)
// 256 threads; 32 rows/CTA; per-thread 4x4 register tile.
// ---------------------------------------------------------------------------
__global__ void proj_kernel(const float* __restrict__ virt, const float* __restrict__ lig)
{
    extern __shared__ float sm[];
    float* Ws = sm;              // 128*128
    float* As = Ws + H * H;      // 32*128
    float* bs = As + 32 * H;     // 128

    int bid = blockIdx.x;
    const float *A, *W, *bias;
    float* C;
    if (bid < 256) { A = virt + bid * 32 * H; W = g_WeffV; bias = g_beffV; C = g_vp + bid * 32 * H; }
    else { int r = bid - 256; A = lig + r * 32 * H; W = g_WeffL; bias = g_beffL; C = g_lb + r * 32 * H; }

    int tid = threadIdx.x;
    for (int i = tid; i < H * H / 4; i += 256)
        ((float4*)Ws)[i] = ((const float4*)W)[i];
    for (int i = tid; i < 32 * H / 4; i += 256)
        ((float4*)As)[i] = ((const float4*)A)[i];
    if (tid < H) bs[tid] = bias[tid];
    __syncthreads();

    int ct = tid & 31, rt = tid >> 5;
    float acc[4][4];
#pragma unroll
    for (int i = 0; i < 4; i++)
#pragma unroll
        for (int j = 0; j < 4; j++) acc[i][j] = bs[ct * 4 + j];

#pragma unroll 4
    for (int k = 0; k < H; k++) {
        float4 w = *(float4*)&Ws[k * H + ct * 4];
#pragma unroll
        for (int i = 0; i < 4; i++) {
            float a = As[(rt * 4 + i) * H + k];
            acc[i][0] += a * w.x; acc[i][1] += a * w.y;
            acc[i][2] += a * w.z; acc[i][3] += a * w.w;
        }
    }
#pragma unroll
    for (int i = 0; i < 4; i++)
        *(float4*)&C[(rt * 4 + i) * H + ct * 4] =
            make_float4(acc[i][0], acc[i][1], acc[i][2], acc[i][3]);
}

// ---------------------------------------------------------------------------
// Kernel 3 (main): one CTA per (b, m). For n-tiles of 128:
//   H1s[k][n'] = relu(lb[k] + vp[n][k])  (shared, transposed, pad 132)
//   register-tiled GEMM vs W2 (shared), relu, dot W3 -> z[n]
// then block softmax over 1024 and attn @ coords.
// ---------------------------------------------------------------------------
__global__ void __launch_bounds__(256, 2)
pair_kernel(const float* __restrict__ vc,
            const int* __restrict__ mask,
            const float* __restrict__ W2, const float* __restrict__ b2,
            const float* __restrict__ W3, const float* __restrict__ b3,
            float* __restrict__ out)
{
    extern __shared__ float sm[];
    float* W2s = sm;               // 8192
    float* lbs = W2s + 8192;       // 128
    float* b2s = lbs + 128;        // 64
    float* w3s = b2s + 64;         // 64
    float* Zp  = w3s + 64;         // 8*128
    float* zs  = Zp + 1024;        // 1024
    float* red = zs + 1024;        // 32
    float* H1s = red + 32;         // 128*132

    int tid = threadIdx.x;
    int bm = blockIdx.x;
    int b = bm >> 6;

    for (int i = tid; i < 8192 / 4; i += 256)
        ((float4*)W2s)[i] = ((const float4*)W2)[i];
    if (tid < 128) lbs[tid] = g_lb[bm * H + tid];
    if (tid < 64) { b2s[tid] = b2[tid]; w3s[tid] = W3[tid]; }
    __syncthreads();

    const float* vpB = g_vp + b * NV * H;
    float b3v = b3[0];

    int nt = tid & 31, jt = tid >> 5;

    for (int t = 0; t < 8; t++) {
        int n0 = t * 128;
        // ---- build H1 tile (transposed) ----
        {
            int n_l = tid >> 1;
            int kb = (tid & 1) * 64;
            const float4* src = (const float4*)(vpB + (size_t)(n0 + n_l) * H + kb);
#pragma unroll
            for (int i = 0; i < 16; i++) {
                float4 v = src[i];
                int k = kb + i * 4;
                H1s[(k + 0) * 132 + n_l] = fmaxf(lbs[k + 0] + v.x, 0.f);
                H1s[(k + 1) * 132 + n_l] = fmaxf(lbs[k + 1] + v.y, 0.f);
                H1s[(k + 2) * 132 + n_l] = fmaxf(lbs[k + 2] + v.z, 0.f);
                H1s[(k + 3) * 132 + n_l] = fmaxf(lbs[k + 3] + v.w, 0.f);
            }
        }
        __syncthreads();

        // ---- register-tiled GEMM: 4 n x 8 j per thread ----
        float acc[4][8];
#pragma unroll
        for (int i = 0; i < 4; i++)
#pragma unroll
            for (int j = 0; j < 8; j++) acc[i][j] = 0.f;

#pragma unroll 4
        for (int k = 0; k < H; k++) {
            float4 hv4 = *(float4*)&H1s[k * 132 + nt * 4];
            float4 w0 = *(float4*)&W2s[k * 64 + jt * 8];
            float4 w1 = *(float4*)&W2s[k * 64 + jt * 8 + 4];
            float hv[4] = {hv4.x, hv4.y, hv4.z, hv4.w};
            float wv[8] = {w0.x, w0.y, w0.z, w0.w, w1.x, w1.y, w1.z, w1.w};
#pragma unroll
            for (int i = 0; i < 4; i++)
#pragma unroll
                for (int j = 0; j < 8; j++)
                    acc[i][j] += hv[i] * wv[j];
        }

        // relu + dot with W3 (partial over this thread's 8 j's)
#pragma unroll
        for (int i = 0; i < 4; i++) {
            float zp = 0.f;
#pragma unroll
            for (int j = 0; j < 8; j++) {
                float h2 = fmaxf(acc[i][j] + b2s[jt * 8 + j], 0.f);
                zp += h2 * w3s[jt * 8 + j];
            }
            Zp[jt * 128 + nt * 4 + i] = zp;
        }
        __syncthreads();
        if (tid < 128) {
            float s = 0.f;
#pragma unroll
            for (int j = 0; j < 8; j++) s += Zp[j * 128 + tid];
            zs[n0 + tid] = s + b3v;
        }
        __syncthreads();
    }

    // ---- softmax over zs[0..1023] ----
    float mx = -3.4e38f;
    for (int n = tid; n < 1024; n += 256) mx = fmaxf(mx, zs[n]);
#pragma unroll
    for (int o = 16; o > 0; o >>= 1) mx = fmaxf(mx, __shfl_xor_sync(0xffffffffu, mx, o));
    if ((tid & 31) == 0) red[tid >> 5] = mx;
    __syncthreads();
    mx = red[0];
#pragma unroll
    for (int j = 1; j < 8; j++) mx = fmaxf(mx, red[j]);

    float sum = 0.f;
    for (int n = tid; n < 1024; n += 256) {
        float e = expf(zs[n] - mx);
        zs[n] = e;
        sum += e;
    }
#pragma unroll
    for (int o = 16; o > 0; o >>= 1) sum += __shfl_xor_sync(0xffffffffu, sum, o);
    __syncthreads();   // everyone done reading red (max phase)
    if ((tid & 31) == 0) red[tid >> 5] = sum;
    __syncthreads();
    sum = 0.f;
#pragma unroll
    for (int j = 0; j < 8; j++) sum += red[j];
    float inv = 1.f / sum;
    float mk = mask[bm] ? 1.f : 0.f;

    float cx = 0.f, cy = 0.f, cz = 0.f;
    const float* vcB = vc + (size_t)b * NV * 3;
    float* attn_out = out + 1536 + (size_t)bm * 1024;
    for (int n = tid; n < 1024; n += 256) {
        float a = zs[n] * inv * mk;
        attn_out[n] = a;
        cx += a * vcB[n * 3 + 0];
        cy += a * vcB[n * 3 + 1];
        cz += a * vcB[n * 3 + 2];
    }
#pragma unroll
    for (int o = 16; o > 0; o >>= 1) {
        cx += __shfl_xor_sync(0xffffffffu, cx, o);
        cy += __shfl_xor_sync(0xffffffffu, cy, o);
        cz += __shfl_xor_sync(0xffffffffu, cz, o);
    }
    __syncthreads();   // everyone done reading red (sum phase)
    if ((tid & 31) == 0) {
        int w = tid >> 5;
        red[w] = cx; red[8 + w] = cy; red[16 + w] = cz;
    }
    __syncthreads();
    if (tid == 0) {
        float X = 0, Y = 0, Z = 0;
#pragma unroll
        for (int j = 0; j < 8; j++) { X += red[j]; Y += red[8 + j]; Z += red[16 + j]; }
        out[bm * 3 + 0] = X;
        out[bm * 3 + 1] = Y;
        out[bm * 3 + 2] = Z;
    }
}

// ---------------------------------------------------------------------------
extern "C" void kernel_launch(void* const* d_in, const int* in_sizes, int n_in,
                              void* d_out, int out_size)
{
    const float* virt = (const float*)d_in[0];
    const float* vcoords = (const float*)d_in[1];
    const float* lig = (const float*)d_in[2];
    // d_in[3], d_in[4]: batch indices — uniform & sorted by construction, unused.
    const int* mask = (const int*)d_in[5];   // bool stored as int32 (R1 rel_err √0.75 signature)
    const float* Wv = (const float*)d_in[6];
    const float* bv = (const float*)d_in[7];
    const float* Wl = (const float*)d_in[8];
    const float* bl = (const float*)d_in[9];
    const float* W1 = (const float*)d_in[10];
    const float* b1 = (const float*)d_in[11];
    const float* W2 = (const float*)d_in[12];
    const float* b2 = (const float*)d_in[13];
    const float* W3 = (const float*)d_in[14];
    const float* b3 = (const float*)d_in[15];
    float* out = (float*)d_out;

    size_t smem2 = (size_t)(H * H + 32 * H + H) * sizeof(float);
    size_t smem3 = (size_t)(8192 + 128 + 64 + 64 + 1024 + 1024 + 32 + 128 * 132) * sizeof(float);
    cudaFuncSetAttribute(proj_kernel, cudaFuncAttributeMaxDynamicSharedMemorySize, (int)smem2);
    cudaFuncSetAttribute(pair_kernel, cudaFuncAttributeMaxDynamicSharedMemorySize, (int)smem3);

    fold_kernel<<<dim3(129, 2), 128>>>(Wv, bv, Wl, bl, W1, b1);
    proj_kernel<<<272, 256, smem2>>>(virt, lig);
    pair_kernel<<<512, 256, smem3>>>(vcoords, mask, W2, b2, W3, b3, out);
}

// round 6
// speedup vs baseline: 1.3590x; 1.3590x over previous
#include <cuda_runtime.h>
#include <cuda_bf16.h>
#include <cstdint>

#define H 128
#define NB 8
#define NV 1024
#define NM 64

// ---------------------------------------------------------------------------
// Scratch (device globals — no allocation allowed)
// ---------------------------------------------------------------------------
__device__ float g_WeffV[H * H];
__device__ float g_beffV[H];
__device__ float g_WeffL[H * H];
__device__ float g_beffL[H];
__device__ float g_vp[NB * NV * H];     // v_part (folded)  [8192,128]
__device__ float g_lb[NB * NM * H];     // l_part + b1      [512,128]
__device__ uint32_t g_W2hi[64 * 64];    // W2 bf16-hi, word[kp][j] (kp = k/2)
__device__ uint32_t g_W2lo[64 * 64];    // W2 bf16-lo residual

// ---------------------------------------------------------------------------
// Helpers
// ---------------------------------------------------------------------------
__device__ __forceinline__ uint32_t pack_bf16(__nv_bfloat16 lo_elem, __nv_bfloat16 hi_elem) {
    return (uint32_t)__bfloat16_as_ushort(lo_elem) |
           ((uint32_t)__bfloat16_as_ushort(hi_elem) << 16);
}

// Split x into bf16 hi + bf16 lo (residual).
__device__ __forceinline__ void bf16_split(float x, __nv_bfloat16& hi, __nv_bfloat16& lo) {
    hi = __float2bfloat16(x);
    lo = __float2bfloat16(x - __bfloat162float(hi));
}

// bf16 tensor-core MMA (sm_80+ baseline PTX): D[16x8] += A[16x16]*B[16x8], f32 accum.
__device__ __forceinline__ void mma_bf16(float c[4], const uint32_t a[4], const uint32_t b[2]) {
    asm volatile(
        "mma.sync.aligned.m16n8k16.row.col.f32.bf16.bf16.f32 "
        "{%0,%1,%2,%3}, {%4,%5,%6,%7}, {%8,%9}, {%0,%1,%2,%3};"
        : "+f"(c[0]), "+f"(c[1]), "+f"(c[2]), "+f"(c[3])
        : "r"(a[0]), "r"(a[1]), "r"(a[2]), "r"(a[3]), "r"(b[0]), "r"(b[1]));
}

// ---------------------------------------------------------------------------
// Kernel 1: fold Wv@W1[H:] and Wl@W1[:H] (+ biases) into single 128x128 mats.
// ---------------------------------------------------------------------------
__global__ void fold_kernel(const float* __restrict__ Wv, const float* __restrict__ bv,
                            const float* __restrict__ Wl, const float* __restrict__ bl,
                            const float* __restrict__ W1, const float* __restrict__ b1)
{
    int h = threadIdx.x;
    int row = blockIdx.x;      // 0..128
    int which = blockIdx.y;    // 0 = virtual, 1 = ligand
    const float* A;
    int w1off;
    if (which == 0) { A = (row < H) ? (Wv + row * H) : bv; w1off = H; }
    else            { A = (row < H) ? (Wl + row * H) : bl; w1off = 0; }
    float a0 = 0.f, a1 = 0.f, a2 = 0.f, a3 = 0.f;
#pragma unroll 8
    for (int hid = 0; hid < H; hid += 4) {
        a0 += A[hid + 0] * W1[(w1off + hid + 0) * H + h];
        a1 += A[hid + 1] * W1[(w1off + hid + 1) * H + h];
        a2 += A[hid + 2] * W1[(w1off + hid + 2) * H + h];
        a3 += A[hid + 3] * W1[(w1off + hid + 3) * H + h];
    }
    float acc = (a0 + a1) + (a2 + a3);
    if (row < H) {
        (which == 0 ? g_WeffV : g_WeffL)[row * H + h] = acc;
    } else {
        if (which == 1) acc += b1[h];
        (which == 0 ? g_beffV : g_beffL)[h] = acc;
    }
}

// ---------------------------------------------------------------------------
// Kernel 1b: split W2 into bf16 hi/lo planes, word layout [kp][j], kp=k/2.
// ---------------------------------------------------------------------------
__global__ void w2split_kernel(const float* __restrict__ W2)
{
    int kp = blockIdx.x, j = threadIdx.x;
    float w0 = W2[(2 * kp) * 64 + j];
    float w1 = W2[(2 * kp + 1) * 64 + j];
    __nv_bfloat16 h0, l0, h1, l1;
    bf16_split(w0, h0, l0);
    bf16_split(w1, h1, l1);
    g_W2hi[kp * 64 + j] = pack_bf16(h0, h1);
    g_W2lo[kp * 64 + j] = pack_bf16(l0, l1);
}

// ---------------------------------------------------------------------------
// Kernel 2: projections (known-good from R2).
// ---------------------------------------------------------------------------
__global__ void proj_kernel(const float* __restrict__ virt, const float* __restrict__ lig)
{
    extern __shared__ float sm[];
    float* Ws = sm;
    float* As = Ws + H * H;
    float* bs = As + 32 * H;

    int bid = blockIdx.x;
    const float *A, *W, *bias;
    float* C;
    if (bid < 256) { A = virt + bid * 32 * H; W = g_WeffV; bias = g_beffV; C = g_vp + bid * 32 * H; }
    else { int r = bid - 256; A = lig + r * 32 * H; W = g_WeffL; bias = g_beffL; C = g_lb + r * 32 * H; }

    int tid = threadIdx.x;
    for (int i = tid; i < H * H / 4; i += 256)
        ((float4*)Ws)[i] = ((const float4*)W)[i];
    for (int i = tid; i < 32 * H / 4; i += 256)
        ((float4*)As)[i] = ((const float4*)A)[i];
    if (tid < H) bs[tid] = bias[tid];
    __syncthreads();

    int ct = tid & 31, rt = tid >> 5;
    float acc[4][4];
#pragma unroll
    for (int i = 0; i < 4; i++)
#pragma unroll
        for (int j = 0; j < 4; j++) acc[i][j] = bs[ct * 4 + j];

#pragma unroll 4
    for (int k = 0; k < H; k++) {
        float4 w = *(float4*)&Ws[k * H + ct * 4];
#pragma unroll
        for (int i = 0; i < 4; i++) {
            float a = As[(rt * 4 + i) * H + k];
            acc[i][0] += a * w.x; acc[i][1] += a * w.y;
            acc[i][2] += a * w.z; acc[i][3] += a * w.w;
        }
    }
#pragma unroll
    for (int i = 0; i < 4; i++)
        *(float4*)&C[(rt * 4 + i) * H + ct * 4] =
            make_float4(acc[i][0], acc[i][1], acc[i][2], acc[i][3]);
}

// ---------------------------------------------------------------------------
// Kernel 3 (main): warp-MMA bf16 split-precision. One CTA per (b, m).
// ---------------------------------------------------------------------------
#define SM_AHI  0
#define SM_ALO  34816
#define SM_BHI  69632
#define SM_BLO  88064
#define SM_ZS   106496
#define SM_LBS  110592
#define SM_B2S  111104
#define SM_W3S  111360
#define SM_RED  111616
#define SM_TOTAL 111744

__global__ void __launch_bounds__(256, 2)
pair_kernel(const float* __restrict__ vc,
            const int* __restrict__ mask,
            const float* __restrict__ b2,
            const float* __restrict__ W3, const float* __restrict__ b3,
            float* __restrict__ out)
{
    extern __shared__ __align__(1024) unsigned char smem[];
    uint32_t* Ahi = (uint32_t*)(smem + SM_AHI);
    uint32_t* Alo = (uint32_t*)(smem + SM_ALO);
    uint32_t* Bhi = (uint32_t*)(smem + SM_BHI);
    uint32_t* Blo = (uint32_t*)(smem + SM_BLO);
    float* zs  = (float*)(smem + SM_ZS);
    float* lbs = (float*)(smem + SM_LBS);
    float* b2s = (float*)(smem + SM_B2S);
    float* w3s = (float*)(smem + SM_W3S);
    float* red = (float*)(smem + SM_RED);

    int tid = threadIdx.x;
    int wid = tid >> 5, lid = tid & 31;
    int bm = blockIdx.x;
    int b = bm >> 6;

    // ---- stage W2 hi/lo into padded SMEM; load lb, b2, w3 ----
    for (int idx = tid; idx < 4096; idx += 256) {
        int kp = idx >> 6, j = idx & 63;
        Bhi[kp * 72 + j] = g_W2hi[idx];
        Blo[kp * 72 + j] = g_W2lo[idx];
    }
    if (tid < 128) lbs[tid] = g_lb[bm * H + tid];
    if (tid < 64) { b2s[tid] = b2[tid]; w3s[tid] = W3[tid]; }
    __syncthreads();   // <-- R4/R5 BUG: this barrier was missing; the t=0
                       //     A-build read lbs[] before producers finished.

    const float* vpB = g_vp + b * NV * H;
    float b3v = b3[0];

    int g = lid >> 2, q = lid & 3;
    int wr = wid & 3;        // row group: rows wr*32 .. +32
    int wc = wid >> 2;       // col group: j    wc*32 .. +32

    for (int t = 0; t < 8; t++) {
        int n0 = t * 128;
        if (tid < 128) zs[n0 + tid] = b3v;
        // ---- build A tile: relu(lb + vp), bf16 hi/lo split ----
        {
            int n = tid >> 1;
            int kb = (tid & 1) * 64;     // k half
            const float4* src = (const float4*)(vpB + (size_t)(n0 + n) * H + kb);
            uint32_t* dhi = Ahi + n * 68 + kb / 2;
            uint32_t* dlo = Alo + n * 68 + kb / 2;
#pragma unroll
            for (int i = 0; i < 16; i++) {
                float4 v = src[i];
                int k = kb + i * 4;
                float x0 = fmaxf(lbs[k + 0] + v.x, 0.f);
                float x1 = fmaxf(lbs[k + 1] + v.y, 0.f);
                float x2 = fmaxf(lbs[k + 2] + v.z, 0.f);
                float x3 = fmaxf(lbs[k + 3] + v.w, 0.f);
                __nv_bfloat16 h0, l0, h1, l1, h2, l2, h3, l3;
                bf16_split(x0, h0, l0); bf16_split(x1, h1, l1);
                bf16_split(x2, h2, l2); bf16_split(x3, h3, l3);
                uint2 whi = make_uint2(pack_bf16(h0, h1), pack_bf16(h2, h3));
                uint2 wlo = make_uint2(pack_bf16(l0, l1), pack_bf16(l2, l3));
                *(uint2*)(dhi + i * 2) = whi;
                *(uint2*)(dlo + i * 2) = wlo;
            }
        }
        __syncthreads();

        // ---- warp MMA: 32n x 32j = 2 m-slabs x 4 j-tiles x 8 k16-steps,
        //      4 cross products hi/lo per fragment pair ----
        float c[2][4][4];
#pragma unroll
        for (int s = 0; s < 2; s++)
#pragma unroll
            for (int jt = 0; jt < 4; jt++)
#pragma unroll
                for (int e = 0; e < 4; e++) c[s][jt][e] = 0.f;

#pragma unroll
        for (int ks = 0; ks < 8; ks++) {
            int wbase = ks * 8 + q;
            uint32_t ah[2][4], al[2][4], bh[4][2], bl[4][2];
#pragma unroll
            for (int s = 0; s < 2; s++) {
                int ro = (wr * 32 + s * 16 + g) * 68 + wbase;
                ah[s][0] = Ahi[ro];            al[s][0] = Alo[ro];
                ah[s][1] = Ahi[ro + 8 * 68];   al[s][1] = Alo[ro + 8 * 68];
                ah[s][2] = Ahi[ro + 4];        al[s][2] = Alo[ro + 4];
                ah[s][3] = Ahi[ro + 8 * 68 + 4]; al[s][3] = Alo[ro + 8 * 68 + 4];
            }
#pragma unroll
            for (int jt = 0; jt < 4; jt++) {
                int bo = wbase * 72 + wc * 32 + jt * 8 + g;
                bh[jt][0] = Bhi[bo];           bl[jt][0] = Blo[bo];
                bh[jt][1] = Bhi[bo + 4 * 72];  bl[jt][1] = Blo[bo + 4 * 72];
            }
#pragma unroll
            for (int s = 0; s < 2; s++)
#pragma unroll
                for (int jt = 0; jt < 4; jt++) {
                    mma_bf16(c[s][jt], al[s], bl[jt]);
                    mma_bf16(c[s][jt], ah[s], bl[jt]);
                    mma_bf16(c[s][jt], al[s], bh[jt]);
                    mma_bf16(c[s][jt], ah[s], bh[jt]);
                }
        }
        __syncthreads();   // all warps done reading A before next build

        // ---- epilogue: relu(+b2)*w3 in regs, quad reduce, atomic z ----
#pragma unroll
        for (int s = 0; s < 2; s++) {
            float z0 = 0.f, z1 = 0.f;
#pragma unroll
            for (int jt = 0; jt < 4; jt++) {
#pragma unroll
                for (int e = 0; e < 2; e++) {
                    int j = wc * 32 + jt * 8 + q * 2 + e;
                    float bb = b2s[j], ww = w3s[j];
                    z0 += fmaxf(c[s][jt][e] + bb, 0.f) * ww;
                    z1 += fmaxf(c[s][jt][2 + e] + bb, 0.f) * ww;
                }
            }
            z0 += __shfl_xor_sync(0xffffffffu, z0, 1);
            z0 += __shfl_xor_sync(0xffffffffu, z0, 2);
            z1 += __shfl_xor_sync(0xffffffffu, z1, 1);
            z1 += __shfl_xor_sync(0xffffffffu, z1, 2);
            if (q == 0) {
                int r = n0 + wr * 32 + s * 16 + g;
                atomicAdd(&zs[r], z0);
                atomicAdd(&zs[r + 8], z1);
            }
        }
    }
    __syncthreads();

    // ---- softmax over zs[0..1023] ----
    float mx = -3.4e38f;
    for (int n = tid; n < 1024; n += 256) mx = fmaxf(mx, zs[n]);
#pragma unroll
    for (int o = 16; o > 0; o >>= 1) mx = fmaxf(mx, __shfl_xor_sync(0xffffffffu, mx, o));
    if (lid == 0) red[wid] = mx;
    __syncthreads();
    mx = red[0];
#pragma unroll
    for (int j = 1; j < 8; j++) mx = fmaxf(mx, red[j]);

    float sum = 0.f;
    for (int n = tid; n < 1024; n += 256) {
        float e = expf(zs[n] - mx);
        zs[n] = e;
        sum += e;
    }
#pragma unroll
    for (int o = 16; o > 0; o >>= 1) sum += __shfl_xor_sync(0xffffffffu, sum, o);
    __syncthreads();
    if (lid == 0) red[wid] = sum;
    __syncthreads();
    sum = 0.f;
#pragma unroll
    for (int j = 0; j < 8; j++) sum += red[j];
    float inv = 1.f / sum;
    float mk = mask[bm] ? 1.f : 0.f;

    float cx = 0.f, cy = 0.f, cz = 0.f;
    const float* vcB = vc + (size_t)b * NV * 3;
    float* attn_out = out + 1536 + (size_t)bm * 1024;
    for (int n = tid; n < 1024; n += 256) {
        float a = zs[n] * inv * mk;
        attn_out[n] = a;
        cx += a * vcB[n * 3 + 0];
        cy += a * vcB[n * 3 + 1];
        cz += a * vcB[n * 3 + 2];
    }
#pragma unroll
    for (int o = 16; o > 0; o >>= 1) {
        cx += __shfl_xor_sync(0xffffffffu, cx, o);
        cy += __shfl_xor_sync(0xffffffffu, cy, o);
        cz += __shfl_xor_sync(0xffffffffu, cz, o);
    }
    __syncthreads();
    if (lid == 0) { red[wid] = cx; red[8 + wid] = cy; red[16 + wid] = cz; }
    __syncthreads();
    if (tid == 0) {
        float X = 0, Y = 0, Z = 0;
#pragma unroll
        for (int j = 0; j < 8; j++) { X += red[j]; Y += red[8 + j]; Z += red[16 + j]; }
        out[bm * 3 + 0] = X;
        out[bm * 3 + 1] = Y;
        out[bm * 3 + 2] = Z;
    }
}

// ---------------------------------------------------------------------------
extern "C" void kernel_launch(void* const* d_in, const int* in_sizes, int n_in,
                              void* d_out, int out_size)
{
    const float* virt = (const float*)d_in[0];
    const float* vcoords = (const float*)d_in[1];
    const float* lig = (const float*)d_in[2];
    const int* mask = (const int*)d_in[5];   // bool stored as int32
    const float* Wv = (const float*)d_in[6];
    const float* bv = (const float*)d_in[7];
    const float* Wl = (const float*)d_in[8];
    const float* bl = (const float*)d_in[9];
    const float* W1 = (const float*)d_in[10];
    const float* b1 = (const float*)d_in[11];
    const float* W2 = (const float*)d_in[12];
    const float* b2 = (const float*)d_in[13];
    const float* W3 = (const float*)d_in[14];
    const float* b3 = (const float*)d_in[15];
    float* out = (float*)d_out;

    size_t smem2 = (size_t)(H * H + 32 * H + H) * sizeof(float);
    cudaFuncSetAttribute(proj_kernel, cudaFuncAttributeMaxDynamicSharedMemorySize, (int)smem2);
    cudaFuncSetAttribute(pair_kernel, cudaFuncAttributeMaxDynamicSharedMemorySize, SM_TOTAL);

    fold_kernel<<<dim3(129, 2), 128>>>(Wv, bv, Wl, bl, W1, b1);
    w2split_kernel<<<64, 64>>>(W2);
    proj_kernel<<<272, 256, smem2>>>(virt, lig);
    pair_kernel<<<512, 256, SM_TOTAL>>>(vcoords, mask, b2, W3, b3, out);
}